// round 9
// baseline (speedup 1.0000x reference)
#include <cuda_runtime.h>
#include <math.h>

#define NBATCH 64
#define NPTS   500
#define DIM    2048
#define KCL    10
#define NITER  10
#define EPSV   1e-6f
#define NSPLIT 4
#define NROWC  (NPTS / NSPLIT)   // 125
#define TILE   32                // 8 warps * 4 rows
#define NTILES 4                 // 32,32,32,29
#define NWARP  8

// ---------------- persistent device scratch (parity double-buffered) --------
__device__ float g_part[2][NBATCH * NSPLIT][KCL * DIM];
__device__ int   g_pcnt[2][NBATCH * NSPLIT][KCL];
__device__ int   g_assign[NBATCH * NPTS];

// ---------------- packed f32x2 helpers ----------------
__device__ __forceinline__ unsigned long long fma2(unsigned long long a,
                                                   unsigned long long b,
                                                   unsigned long long c) {
    unsigned long long d;
    asm("fma.rn.f32x2 %0, %1, %2, %3;" : "=l"(d) : "l"(a), "l"(b), "l"(c));
    return d;
}
__device__ __forceinline__ float2 unpack2(unsigned long long v) {
    float2 r;
    asm("mov.b64 {%0, %1}, %2;" : "=f"(r.x), "=f"(r.y) : "l"(v));
    return r;
}

// ---------------- init: parity-0 partials = first-K features ----------------
__global__ void init_kernel(const float* __restrict__ f) {
    int b = blockIdx.x / KCL, k = blockIdx.x % KCL;
    int d = threadIdx.x * 4;
    float4 z4 = make_float4(0.f, 0.f, 0.f, 0.f);
    float4 v = *(const float4*)(f + ((size_t)(b * NPTS + k)) * DIM + d);
    *(float4*)(&g_part[0][b * 4 + 0][k * DIM + d]) = v;
    *(float4*)(&g_part[0][b * 4 + 1][k * DIM + d]) = z4;
    *(float4*)(&g_part[0][b * 4 + 2][k * DIM + d]) = z4;
    *(float4*)(&g_part[0][b * 4 + 3][k * DIM + d]) = z4;
    if (threadIdx.x == 0) {
        g_pcnt[0][b * 4 + 0][k] = 1;
        g_pcnt[0][b * 4 + 1][k] = 0;
        g_pcnt[0][b * 4 + 2][k] = 0;
        g_pcnt[0][b * 4 + 3][k] = 0;
    }
}

// FMA block over 5 clusters (half-K pass): acc[5][4]
#define FMABLOCK5(C0, C1, C2, C3)                                             \
    _Pragma("unroll")                                                         \
    for (int k = 0; k < 5; k++) {                                             \
        ulonglong2 cc = *(const ulonglong2*)(scd + (size_t)k * DIM);          \
        acc[k][0] = fma2((C0).x, cc.x, acc[k][0]);                            \
        acc[k][1] = fma2((C1).x, cc.x, acc[k][1]);                            \
        acc[k][2] = fma2((C2).x, cc.x, acc[k][2]);                            \
        acc[k][3] = fma2((C3).x, cc.x, acc[k][3]);                            \
        acc[k][0] = fma2((C0).y, cc.y, acc[k][0]);                            \
        acc[k][1] = fma2((C1).y, cc.y, acc[k][1]);                            \
        acc[k][2] = fma2((C2).y, cc.y, acc[k][2]);                            \
        acc[k][3] = fma2((C3).y, cc.y, acc[k][3]);                            \
    }

// ---------------- fused iteration: 256 threads, 2 CTAs/SM -------------------
__global__ __launch_bounds__(256, 2) void iter_kernel(const float* __restrict__ feats,
                                                      int rd) {
    extern __shared__ float smem[];
    float* sc      = smem;                    // [KCL][DIM] centroids
    float* schalf  = smem + KCL * DIM;        // [16]
    float* sinv    = schalf + 16;             // [16]
    int*   sa      = (int*)(sinv + 16);       // [TILE]
    int*   ssorted = sa + TILE;               // [TILE]
    int*   soff    = ssorted + TILE;          // [12]
    int*   scnt    = soff + 12;               // [16]

    int bid = blockIdx.x;
    int b = bid >> 2, sp = bid & 3;
    int wr = rd ^ 1;
    int tid = threadIdx.x, warp = tid >> 5, lane = tid & 31;
    float4 z4 = make_float4(0.f, 0.f, 0.f, 0.f);

    // ---- fused reduce: centroids = sum(4 partials) * inv; zero own wr slot --
    if (tid < KCL) {
        int c = g_pcnt[rd][b * 4 + 0][tid] + g_pcnt[rd][b * 4 + 1][tid]
              + g_pcnt[rd][b * 4 + 2][tid] + g_pcnt[rd][b * 4 + 3][tid];
        sinv[tid] = 1.0f / (float)(c > 1 ? c : 1);
        scnt[tid] = 0;
    }
    __syncthreads();
    {
        const float4* q0 = (const float4*)g_part[rd][b * 4 + 0];
        const float4* q1 = (const float4*)g_part[rd][b * 4 + 1];
        const float4* q2 = (const float4*)g_part[rd][b * 4 + 2];
        const float4* q3 = (const float4*)g_part[rd][b * 4 + 3];
        float4* zw = (float4*)g_part[wr][bid];
        for (int i = tid; i < KCL * DIM / 4; i += 256) {
            float4 a = q0[i], c = q1[i], d = q2[i], e = q3[i];
            float inv = sinv[i >> 9];
            ((float4*)sc)[i] = make_float4(
                (a.x + c.x + d.x + e.x) * inv, (a.y + c.y + d.y + e.y) * inv,
                (a.z + c.z + d.z + e.z) * inv, (a.w + c.w + d.w + e.w) * inv);
            zw[i] = z4;
        }
    }
    __syncthreads();

    for (int k = warp; k < KCL; k += NWARP) {
        float s = 0.f;
        for (int d = lane; d < DIM; d += 32) {
            float c = sc[k * DIM + d];
            s = fmaf(c, c, s);
        }
        #pragma unroll
        for (int o = 16; o; o >>= 1) s += __shfl_xor_sync(0xffffffffu, s, o);
        if (lane == 0) schalf[k] = 0.5f * s;
    }
    __syncthreads();

    const float* fb = feats + ((size_t)b * NPTS + (size_t)sp * NROWC) * DIM;
    int gabase = b * NPTS + sp * NROWC;
    int mywd = warp * 256 + lane * 4;

    for (int tile = 0; tile < NTILES; tile++) {
        int tbase = tile * TILE;
        int nrows = NROWC - tbase; if (nrows > TILE) nrows = TILE;

        // ---------- phase A: 4 rows per warp, TWO half-K passes ----------
        int r0i = tbase + warp * 4;
        int i0 = min(r0i + 0, NROWC - 1);
        int i1 = min(r0i + 1, NROWC - 1);
        int i2 = min(r0i + 2, NROWC - 1);
        int i3 = min(r0i + 3, NROWC - 1);
        const float* p0 = fb + (size_t)i0 * DIM + lane * 4;
        const float* p1 = fb + (size_t)i1 * DIM + lane * 4;
        const float* p2 = fb + (size_t)i2 * DIM + lane * 4;
        const float* p3 = fb + (size_t)i3 * DIM + lane * 4;

        float dot[KCL][4];

        #pragma unroll 1
        for (int h = 0; h < 2; h++) {
            const float* sch = sc + (size_t)(h * 5) * DIM;

            unsigned long long acc[5][4];
            #pragma unroll
            for (int k = 0; k < 5; k++)
                #pragma unroll
                for (int r = 0; r < 4; r++) acc[k][r] = 0ull;

            ulonglong2 c0 = *(const ulonglong2*)p0;
            ulonglong2 c1 = *(const ulonglong2*)p1;
            ulonglong2 c2 = *(const ulonglong2*)p2;
            ulonglong2 c3 = *(const ulonglong2*)p3;
            #pragma unroll 1
            for (int ch = 0; ch < 15; ch++) {
                int nofs = (ch + 1) * 128;
                ulonglong2 n0 = *(const ulonglong2*)(p0 + nofs);
                ulonglong2 n1 = *(const ulonglong2*)(p1 + nofs);
                ulonglong2 n2 = *(const ulonglong2*)(p2 + nofs);
                ulonglong2 n3 = *(const ulonglong2*)(p3 + nofs);
                const float* scd = sch + ch * 128 + lane * 4;
                FMABLOCK5(c0, c1, c2, c3);
                c0 = n0; c1 = n1; c2 = n2; c3 = n3;
            }
            {
                const float* scd = sch + 15 * 128 + lane * 4;
                FMABLOCK5(c0, c1, c2, c3);
            }

            #pragma unroll
            for (int k = 0; k < 5; k++) {
                #pragma unroll
                for (int r = 0; r < 4; r++) {
                    float2 v = unpack2(acc[k][r]);
                    float s = v.x + v.y;
                    #pragma unroll
                    for (int o = 16; o; o >>= 1)
                        s += __shfl_xor_sync(0xffffffffu, s, o);
                    dot[h * 5 + k][r] = s;
                }
            }
        }

        #pragma unroll
        for (int r = 0; r < 4; r++) {
            if (lane == r) {
                float best = schalf[0] - dot[0][r];
                int bi = 0;
                #pragma unroll
                for (int k = 1; k < KCL; k++) {
                    float s = schalf[k] - dot[k][r];
                    if (s < best) { best = s; bi = k; }
                }
                bool valid = (r0i + r) < NROWC;
                sa[warp * 4 + r] = valid ? bi : -1;
                if (valid) g_assign[gabase + r0i + r] = bi;
            }
        }
        __syncthreads();

        // ---------- counting sort (warp 0, single 32-wide pass) ----------
        if (warp == 0) {
            int a = (lane < nrows) ? sa[lane] : -1;
            int mycnt = 0;
            unsigned mybal = 0;
            #pragma unroll
            for (int k = 0; k < KCL; k++) {
                unsigned m = __ballot_sync(0xffffffffu, a == k);
                if (lane == k) mycnt = __popc(m);
                if (a == k) mybal = m;
            }
            int v = (lane < KCL) ? mycnt : 0;
            #pragma unroll
            for (int o = 1; o < 16; o <<= 1) {
                int t = __shfl_up_sync(0xffffffffu, v, o);
                if (lane >= o) v += t;
            }
            int excl = v - ((lane < KCL) ? mycnt : 0);
            if (lane < KCL) { soff[lane] = excl; scnt[lane] += mycnt; }
            if (lane == KCL - 1) soff[KCL] = v;
            __syncwarp();
            if (a >= 0) {
                int rank = __popc(mybal & ((1u << lane) - 1u));
                ssorted[soff[a] + rank] = lane;
            }
        }
        __syncthreads();

        // ---------- phase B: sorted lists -> register sums -> g_part RMW ----
        {
            const float* fsl = fb + (size_t)tbase * DIM + mywd;
            float* gslice = &g_part[wr][bid][mywd];
            #pragma unroll
            for (int k = 0; k < KCL; k++) {
                int s0 = soff[k], s1 = soff[k + 1];
                if (s0 == s1) continue;
                float* gp = gslice + (size_t)k * DIM;
                float4 o0 = *(const float4*)(gp);
                float4 o1 = *(const float4*)(gp + 128);
                float4 a0 = z4, a1 = z4;
                int idx = s0;
                for (; idx + 2 <= s1; idx += 2) {
                    int na = ssorted[idx], nb = ssorted[idx + 1];
                    const float* ra = fsl + (size_t)na * DIM;
                    const float* rb = fsl + (size_t)nb * DIM;
                    float4 fa0 = *(const float4*)(ra);
                    float4 fa1 = *(const float4*)(ra + 128);
                    float4 fb0 = *(const float4*)(rb);
                    float4 fb1 = *(const float4*)(rb + 128);
                    a0.x += fa0.x; a0.y += fa0.y; a0.z += fa0.z; a0.w += fa0.w;
                    a1.x += fa1.x; a1.y += fa1.y; a1.z += fa1.z; a1.w += fa1.w;
                    a0.x += fb0.x; a0.y += fb0.y; a0.z += fb0.z; a0.w += fb0.w;
                    a1.x += fb1.x; a1.y += fb1.y; a1.z += fb1.z; a1.w += fb1.w;
                }
                if (idx < s1) {
                    int na = ssorted[idx];
                    const float* ra = fsl + (size_t)na * DIM;
                    float4 fa0 = *(const float4*)(ra);
                    float4 fa1 = *(const float4*)(ra + 128);
                    a0.x += fa0.x; a0.y += fa0.y; a0.z += fa0.z; a0.w += fa0.w;
                    a1.x += fa1.x; a1.y += fa1.y; a1.z += fa1.z; a1.w += fa1.w;
                }
                o0.x += a0.x; o0.y += a0.y; o0.z += a0.z; o0.w += a0.w;
                o1.x += a1.x; o1.y += a1.y; o1.z += a1.z; o1.w += a1.w;
                *(float4*)(gp)       = o0;
                *(float4*)(gp + 128) = o1;
            }
        }
        __syncthreads();
    }

    if (tid < KCL) g_pcnt[wr][bid][tid] = scnt[tid];
}

// ---------------- final GeM pooling (empty cluster -> 0) ----------------
__global__ __launch_bounds__(512) void final_kernel(const float* __restrict__ feats,
                                                    const float* __restrict__ pp,
                                                    float* __restrict__ out) {
    __shared__ int sa[NPTS];
    int b = blockIdx.x / KCL, k = blockIdx.x % KCL;
    int tid = threadIdx.x;
    for (int i = tid; i < NPTS; i += 512) sa[i] = g_assign[b * NPTS + i];
    __syncthreads();

    float pv = pp[0];
    bool p3 = (pv == 3.0f);
    const float* fb = feats + (size_t)b * NPTS * DIM + tid * 4;

    float ax = 0.f, ay = 0.f, az = 0.f, aw = 0.f;
    int cnt = 0;
    if (p3) {
        #pragma unroll 2
        for (int n = 0; n < NPTS; n++) {
            if (sa[n] == k) {
                cnt++;
                float4 f = *(const float4*)(fb + (size_t)n * DIM);
                float x = fmaxf(f.x, EPSV), y = fmaxf(f.y, EPSV);
                float z = fmaxf(f.z, EPSV), w = fmaxf(f.w, EPSV);
                ax += x * x * x; ay += y * y * y; az += z * z * z; aw += w * w * w;
            }
        }
    } else {
        for (int n = 0; n < NPTS; n++) {
            if (sa[n] == k) {
                cnt++;
                float4 f = *(const float4*)(fb + (size_t)n * DIM);
                ax += powf(fmaxf(f.x, EPSV), pv);
                ay += powf(fmaxf(f.y, EPSV), pv);
                az += powf(fmaxf(f.z, EPSV), pv);
                aw += powf(fmaxf(f.w, EPSV), pv);
            }
        }
    }

    float inv = 1.0f / (float)(cnt > 1 ? cnt : 1);
    size_t oi = (size_t)(b * KCL + k) * DIM + tid * 4;
    float4 o;
    if (cnt > 0) {
        if (p3) {
            o = make_float4(cbrtf(ax * inv), cbrtf(ay * inv),
                            cbrtf(az * inv), cbrtf(aw * inv));
        } else {
            float ip = 1.0f / pv;
            o = make_float4(powf(ax * inv, ip), powf(ay * inv, ip),
                            powf(az * inv, ip), powf(aw * inv, ip));
        }
    } else {
        o = make_float4(0.f, 0.f, 0.f, 0.f);
    }
    *(float4*)(out + oi) = o;
}

// ---------------- launch ----------------
extern "C" void kernel_launch(void* const* d_in, const int* in_sizes, int n_in,
                              void* d_out, int out_size) {
    const float* feats = (const float*)d_in[0];
    const float* p     = (const float*)d_in[1];
    float* out         = (float*)d_out;

    const int smem_iter = (KCL * DIM + 32) * sizeof(float)
                        + (TILE + TILE + 12 + 16) * sizeof(int);
    cudaFuncSetAttribute(iter_kernel,
                         cudaFuncAttributeMaxDynamicSharedMemorySize, smem_iter);

    init_kernel<<<NBATCH * KCL, 512>>>(feats);
    for (int it = 0; it < NITER; it++)
        iter_kernel<<<NBATCH * NSPLIT, 256, smem_iter>>>(feats, it & 1);
    final_kernel<<<NBATCH * KCL, 512>>>(feats, p, out);
}

// round 10
// speedup vs baseline: 1.2982x; 1.2982x over previous
#include <cuda_runtime.h>
#include <math.h>

#define NBATCH 64
#define NPTS   500
#define DIM    2048
#define KCL    10
#define NITER  10
#define EPSV   1e-6f
#define NSPLIT 2
#define NROWC  (NPTS / NSPLIT)   // 250
#define TILE   64                // 16 warps * 4 rows
#define NTILES 4                 // 64,64,64,58
#define CHUNKF 128               // floats per chunk per row
#define NCHUNK (DIM / CHUNKF)    // 16
#define NBUF   4

// ---------------- persistent device scratch (parity double-buffered) --------
__device__ float g_part[2][NBATCH * NSPLIT][KCL * DIM];
__device__ int   g_pcnt[2][NBATCH * NSPLIT][KCL];
__device__ int   g_assign[NBATCH * NPTS];

// ---------------- helpers ----------------
__device__ __forceinline__ unsigned long long fma2(unsigned long long a,
                                                   unsigned long long b,
                                                   unsigned long long c) {
    unsigned long long d;
    asm("fma.rn.f32x2 %0, %1, %2, %3;" : "=l"(d) : "l"(a), "l"(b), "l"(c));
    return d;
}
__device__ __forceinline__ float2 unpack2(unsigned long long v) {
    float2 r;
    asm("mov.b64 {%0, %1}, %2;" : "=f"(r.x), "=f"(r.y) : "l"(v));
    return r;
}
__device__ __forceinline__ void cp16(unsigned int dst, const void* src) {
    asm volatile("cp.async.cg.shared.global [%0], [%1], 16;"
                 :: "r"(dst), "l"(src));
}
#define CP_COMMIT()  asm volatile("cp.async.commit_group;" ::: "memory")
#define CP_WAIT2()   asm volatile("cp.async.wait_group 2;"  ::: "memory")

// ---------------- init: parity-0 partials = first-K features ----------------
__global__ void init_kernel(const float* __restrict__ f) {
    int b = blockIdx.x / KCL, k = blockIdx.x % KCL;
    int d = threadIdx.x * 4;
    float4 z4 = make_float4(0.f, 0.f, 0.f, 0.f);
    float4 v = *(const float4*)(f + ((size_t)(b * NPTS + k)) * DIM + d);
    *(float4*)(&g_part[0][b * 2 + 0][k * DIM + d]) = v;
    *(float4*)(&g_part[0][b * 2 + 1][k * DIM + d]) = z4;
    if (threadIdx.x == 0) {
        g_pcnt[0][b * 2 + 0][k] = 1;
        g_pcnt[0][b * 2 + 1][k] = 0;
    }
}

// FMA block: same-acc updates spaced 4 apart
#define FMABLOCK(C0, C1, C2, C3)                                              \
    _Pragma("unroll")                                                         \
    for (int k = 0; k < KCL; k++) {                                           \
        ulonglong2 cc = *(const ulonglong2*)(scd + (size_t)k * DIM);          \
        acc[k][0] = fma2((C0).x, cc.x, acc[k][0]);                            \
        acc[k][1] = fma2((C1).x, cc.x, acc[k][1]);                            \
        acc[k][2] = fma2((C2).x, cc.x, acc[k][2]);                            \
        acc[k][3] = fma2((C3).x, cc.x, acc[k][3]);                            \
        acc[k][0] = fma2((C0).y, cc.y, acc[k][0]);                            \
        acc[k][1] = fma2((C1).y, cc.y, acc[k][1]);                            \
        acc[k][2] = fma2((C2).y, cc.y, acc[k][2]);                            \
        acc[k][3] = fma2((C3).y, cc.y, acc[k][3]);                            \
    }

// ---------------- fused iteration: cp.async chunk pipeline ------------------
// grid = 128 (b, sp), block = 512, ~214KB smem, 1 CTA/SM.
__global__ __launch_bounds__(512, 1) void iter_kernel(const float* __restrict__ feats,
                                                      int rd) {
    extern __shared__ float smem[];
    float* sc     = smem;                          // [KCL][DIM]
    float* fbuf   = smem + KCL * DIM;              // [NBUF][TILE][CHUNKF]
    float* schalf = fbuf + NBUF * TILE * CHUNKF;   // [16]
    float* sinv   = schalf + 16;                   // [16]
    int*   sa      = (int*)(sinv + 16);            // [TILE]
    int*   ssorted = sa + TILE;                    // [TILE]
    int*   soff    = ssorted + TILE;               // [12]
    int*   srun    = soff + 12;                    // [10]
    int*   scnt    = srun + 10;                    // [16]

    int bid = blockIdx.x;
    int b = bid >> 1, sp = bid & 1;
    int wr = rd ^ 1;
    int tid = threadIdx.x, warp = tid >> 5, lane = tid & 31;
    float4 z4 = make_float4(0.f, 0.f, 0.f, 0.f);

    unsigned int fba = (unsigned int)__cvta_generic_to_shared(fbuf);

    // ---- fused reduce: centroids = (part0 + part1) * inv; zero wr slot -----
    if (tid < KCL) {
        int c = g_pcnt[rd][b * 2 + 0][tid] + g_pcnt[rd][b * 2 + 1][tid];
        sinv[tid] = 1.0f / (float)(c > 1 ? c : 1);
        scnt[tid] = 0;
    }
    __syncthreads();
    {
        const float4* q0 = (const float4*)g_part[rd][b * 2 + 0];
        const float4* q1 = (const float4*)g_part[rd][b * 2 + 1];
        float4* zw = (float4*)g_part[wr][bid];
        for (int i = tid; i < KCL * DIM / 4; i += 512) {
            float4 a = q0[i], c = q1[i];
            float inv = sinv[i >> 9];
            ((float4*)sc)[i] = make_float4((a.x + c.x) * inv, (a.y + c.y) * inv,
                                           (a.z + c.z) * inv, (a.w + c.w) * inv);
            zw[i] = z4;
        }
    }
    __syncthreads();

    if (warp < KCL) {
        float s = 0.f;
        for (int d = lane; d < DIM; d += 32) {
            float c = sc[warp * DIM + d];
            s = fmaf(c, c, s);
        }
        #pragma unroll
        for (int o = 16; o; o >>= 1) s += __shfl_xor_sync(0xffffffffu, s, o);
        if (lane == 0) schalf[warp] = 0.5f * s;
    }
    __syncthreads();

    const float* fb = feats + ((size_t)b * NPTS + (size_t)sp * NROWC) * DIM;
    int gabase = b * NPTS + sp * NROWC;
    int mywd = warp * 128 + lane * 4;              // phase-B slice: 128 dims/warp

    // per-thread cp.async op coordinates (4 ops of 16B -> 64 rows x 512B)
    int cpr[4], cps[4];
    #pragma unroll
    for (int t = 0; t < 4; t++) {
        int i = tid + t * 512;
        cpr[t] = i >> 5;          // row within tile
        cps[t] = (i & 31) * 16;   // byte slot within 512B chunk-row
    }

    for (int tile = 0; tile < NTILES; tile++) {
        int tbase = tile * TILE;
        int nrows = NROWC - tbase; if (nrows > TILE) nrows = TILE;

        // ---------- prologue: issue chunks 0..2 ----------
        #pragma unroll
        for (int c = 0; c < 3; c++) {
            unsigned int dbase = fba + (unsigned int)(c * TILE * CHUNKF * 4);
            #pragma unroll
            for (int t = 0; t < 4; t++) {
                int g = min(tbase + cpr[t], NROWC - 1);
                const char* src = (const char*)(fb + (size_t)g * DIM + c * CHUNKF) + cps[t];
                cp16(dbase + (unsigned int)(cpr[t] * CHUNKF * 4) + cps[t], src);
            }
            CP_COMMIT();
        }

        // ---------- phase A: chunk-pipelined FMA ----------
        unsigned long long acc[KCL][4];
        #pragma unroll
        for (int k = 0; k < KCL; k++)
            #pragma unroll
            for (int r = 0; r < 4; r++) acc[k][r] = 0ull;

        #pragma unroll 1
        for (int ch = 0; ch < NCHUNK; ch++) {
            CP_WAIT2();          // chunk ch complete (pending <= 2)
            __syncthreads();     // visible to all warps; prior buffer free

            const float* fr = fbuf + (size_t)(ch & 3) * (TILE * CHUNKF)
                            + (size_t)(warp * 4) * CHUNKF + lane * 4;
            ulonglong2 c0 = *(const ulonglong2*)(fr);
            ulonglong2 c1 = *(const ulonglong2*)(fr + CHUNKF);
            ulonglong2 c2 = *(const ulonglong2*)(fr + 2 * CHUNKF);
            ulonglong2 c3 = *(const ulonglong2*)(fr + 3 * CHUNKF);
            const float* scd = sc + ch * CHUNKF + lane * 4;
            FMABLOCK(c0, c1, c2, c3);

            if (ch < NCHUNK - 3) {
                int nc = ch + 3;
                unsigned int dbase = fba + (unsigned int)((nc & 3) * TILE * CHUNKF * 4);
                #pragma unroll
                for (int t = 0; t < 4; t++) {
                    int g = min(tbase + cpr[t], NROWC - 1);
                    const char* src = (const char*)(fb + (size_t)g * DIM + nc * CHUNKF) + cps[t];
                    cp16(dbase + (unsigned int)(cpr[t] * CHUNKF * 4) + cps[t], src);
                }
            }
            CP_COMMIT();         // always commit (empty group ok) to keep count
        }

        // reduce + argmin
        float dot[KCL][4];
        #pragma unroll
        for (int k = 0; k < KCL; k++) {
            #pragma unroll
            for (int r = 0; r < 4; r++) {
                float2 v = unpack2(acc[k][r]);
                float s = v.x + v.y;
                #pragma unroll
                for (int o = 16; o; o >>= 1)
                    s += __shfl_xor_sync(0xffffffffu, s, o);
                dot[k][r] = s;
            }
        }
        int r0i = tbase + warp * 4;
        #pragma unroll
        for (int r = 0; r < 4; r++) {
            if (lane == r) {
                float best = schalf[0] - dot[0][r];
                int bi = 0;
                #pragma unroll
                for (int k = 1; k < KCL; k++) {
                    float s = schalf[k] - dot[k][r];
                    if (s < best) { best = s; bi = k; }
                }
                bool valid = (r0i + r) < NROWC;
                sa[warp * 4 + r] = valid ? bi : -1;
                if (valid) g_assign[gabase + r0i + r] = bi;
            }
        }
        __syncthreads();

        // ---------- counting sort (warp 0, two 32-wide passes) ----------
        if (warp == 0) {
            int mycnt = 0;
            #pragma unroll
            for (int q = 0; q < 2; q++) {
                int n = q * 32 + lane;
                int a = (n < nrows) ? sa[n] : -1;
                #pragma unroll
                for (int k = 0; k < KCL; k++) {
                    unsigned m = __ballot_sync(0xffffffffu, a == k);
                    if (lane == k) mycnt += __popc(m);
                }
            }
            int v = (lane < KCL) ? mycnt : 0;
            #pragma unroll
            for (int o = 1; o < 16; o <<= 1) {
                int t = __shfl_up_sync(0xffffffffu, v, o);
                if (lane >= o) v += t;
            }
            int excl = v - ((lane < KCL) ? mycnt : 0);
            if (lane < KCL) { soff[lane] = excl; srun[lane] = excl; scnt[lane] += mycnt; }
            if (lane == KCL - 1) soff[KCL] = v;
            __syncwarp();
            #pragma unroll
            for (int q = 0; q < 2; q++) {
                int n = q * 32 + lane;
                int a = (n < nrows) ? sa[n] : -1;
                unsigned mybal = 0;
                #pragma unroll
                for (int k = 0; k < KCL; k++) {
                    unsigned m = __ballot_sync(0xffffffffu, a == k);
                    if (a == k) mybal = m;
                }
                if (a >= 0) {
                    int rank = __popc(mybal & ((1u << lane) - 1u));
                    ssorted[srun[a] + rank] = n;
                    if (rank == __popc(mybal) - 1) srun[a] += rank + 1;
                }
                __syncwarp();
            }
        }
        __syncthreads();

        // ---------- phase B: sorted lists -> register sums -> g_part RMW ----
        {
            const float* fsl = fb + (size_t)tbase * DIM + mywd;
            float* gslice = &g_part[wr][bid][mywd];
            #pragma unroll
            for (int k = 0; k < KCL; k++) {
                int s0 = soff[k], s1 = soff[k + 1];
                if (s0 == s1) continue;
                float* gp = gslice + (size_t)k * DIM;
                float4 o0 = *(const float4*)gp;
                float4 a4 = z4, b4 = z4;
                int idx = s0;
                for (; idx + 2 <= s1; idx += 2) {
                    int na = ssorted[idx], nb = ssorted[idx + 1];
                    float4 fa = *(const float4*)(fsl + (size_t)na * DIM);
                    float4 fc = *(const float4*)(fsl + (size_t)nb * DIM);
                    a4.x += fa.x; a4.y += fa.y; a4.z += fa.z; a4.w += fa.w;
                    b4.x += fc.x; b4.y += fc.y; b4.z += fc.z; b4.w += fc.w;
                }
                if (idx < s1) {
                    int na = ssorted[idx];
                    float4 fa = *(const float4*)(fsl + (size_t)na * DIM);
                    a4.x += fa.x; a4.y += fa.y; a4.z += fa.z; a4.w += fa.w;
                }
                o0.x += a4.x + b4.x; o0.y += a4.y + b4.y;
                o0.z += a4.z + b4.z; o0.w += a4.w + b4.w;
                *(float4*)gp = o0;
            }
        }
        // no trailing barrier: next tile's first chunk-barrier covers ordering
    }

    __syncthreads();
    if (tid < KCL) g_pcnt[wr][bid][tid] = scnt[tid];
}

// ---------------- final GeM pooling (empty cluster -> 0) ----------------
__global__ __launch_bounds__(512) void final_kernel(const float* __restrict__ feats,
                                                    const float* __restrict__ pp,
                                                    float* __restrict__ out) {
    __shared__ int sa[NPTS];
    int b = blockIdx.x / KCL, k = blockIdx.x % KCL;
    int tid = threadIdx.x;
    for (int i = tid; i < NPTS; i += 512) sa[i] = g_assign[b * NPTS + i];
    __syncthreads();

    float pv = pp[0];
    bool p3 = (pv == 3.0f);
    const float* fb = feats + (size_t)b * NPTS * DIM + tid * 4;

    float ax = 0.f, ay = 0.f, az = 0.f, aw = 0.f;
    int cnt = 0;
    if (p3) {
        #pragma unroll 2
        for (int n = 0; n < NPTS; n++) {
            if (sa[n] == k) {
                cnt++;
                float4 f = *(const float4*)(fb + (size_t)n * DIM);
                float x = fmaxf(f.x, EPSV), y = fmaxf(f.y, EPSV);
                float z = fmaxf(f.z, EPSV), w = fmaxf(f.w, EPSV);
                ax += x * x * x; ay += y * y * y; az += z * z * z; aw += w * w * w;
            }
        }
    } else {
        for (int n = 0; n < NPTS; n++) {
            if (sa[n] == k) {
                cnt++;
                float4 f = *(const float4*)(fb + (size_t)n * DIM);
                ax += powf(fmaxf(f.x, EPSV), pv);
                ay += powf(fmaxf(f.y, EPSV), pv);
                az += powf(fmaxf(f.z, EPSV), pv);
                aw += powf(fmaxf(f.w, EPSV), pv);
            }
        }
    }

    float inv = 1.0f / (float)(cnt > 1 ? cnt : 1);
    size_t oi = (size_t)(b * KCL + k) * DIM + tid * 4;
    float4 o;
    if (cnt > 0) {
        if (p3) {
            o = make_float4(cbrtf(ax * inv), cbrtf(ay * inv),
                            cbrtf(az * inv), cbrtf(aw * inv));
        } else {
            float ip = 1.0f / pv;
            o = make_float4(powf(ax * inv, ip), powf(ay * inv, ip),
                            powf(az * inv, ip), powf(aw * inv, ip));
        }
    } else {
        o = make_float4(0.f, 0.f, 0.f, 0.f);
    }
    *(float4*)(out + oi) = o;
}

// ---------------- launch ----------------
extern "C" void kernel_launch(void* const* d_in, const int* in_sizes, int n_in,
                              void* d_out, int out_size) {
    const float* feats = (const float*)d_in[0];
    const float* p     = (const float*)d_in[1];
    float* out         = (float*)d_out;

    const int smem_iter = (KCL * DIM + NBUF * TILE * CHUNKF + 32) * sizeof(float)
                        + (TILE + TILE + 12 + 10 + 16) * sizeof(int);
    cudaFuncSetAttribute(iter_kernel,
                         cudaFuncAttributeMaxDynamicSharedMemorySize, smem_iter);

    init_kernel<<<NBATCH * KCL, 512>>>(feats);
    for (int it = 0; it < NITER; it++)
        iter_kernel<<<NBATCH * NSPLIT, 512, smem_iter>>>(feats, it & 1);
    final_kernel<<<NBATCH * KCL, 512>>>(feats, p, out);
}

// round 11
// speedup vs baseline: 1.3992x; 1.0778x over previous
#include <cuda_runtime.h>
#include <math.h>

#define NBATCH 64
#define NPTS   500
#define DIM    2048
#define KCL    10
#define NITER  10
#define EPSV   1e-6f
#define NSPLIT 2
#define NROWC  (NPTS / NSPLIT)   // 250
#define TILE   64                // 16 warps * 4 rows
#define NTILES 4                 // 64,64,64,58
#define CHUNKF 128               // floats per chunk per row
#define NCHUNK (DIM / CHUNKF)    // 16
#define NBUF   4                 // per-warp ring depth

// ---------------- persistent device scratch (parity double-buffered) --------
__device__ float g_part[2][NBATCH * NSPLIT][KCL * DIM];
__device__ int   g_pcnt[2][NBATCH * NSPLIT][KCL];
__device__ int   g_assign[NBATCH * NPTS];

// ---------------- helpers ----------------
__device__ __forceinline__ unsigned long long fma2(unsigned long long a,
                                                   unsigned long long b,
                                                   unsigned long long c) {
    unsigned long long d;
    asm("fma.rn.f32x2 %0, %1, %2, %3;" : "=l"(d) : "l"(a), "l"(b), "l"(c));
    return d;
}
__device__ __forceinline__ float2 unpack2(unsigned long long v) {
    float2 r;
    asm("mov.b64 {%0, %1}, %2;" : "=f"(r.x), "=f"(r.y) : "l"(v));
    return r;
}
__device__ __forceinline__ void cp16(unsigned int dst, const void* src) {
    asm volatile("cp.async.cg.shared.global [%0], [%1], 16;"
                 :: "r"(dst), "l"(src));
}
#define CP_COMMIT()  asm volatile("cp.async.commit_group;" ::: "memory")
#define CP_WAIT2()   asm volatile("cp.async.wait_group 2;"  ::: "memory")

// ---------------- init: parity-0 partials = first-K features ----------------
__global__ void init_kernel(const float* __restrict__ f) {
    int b = blockIdx.x / KCL, k = blockIdx.x % KCL;
    int d = threadIdx.x * 4;
    float4 z4 = make_float4(0.f, 0.f, 0.f, 0.f);
    float4 v = *(const float4*)(f + ((size_t)(b * NPTS + k)) * DIM + d);
    *(float4*)(&g_part[0][b * 2 + 0][k * DIM + d]) = v;
    *(float4*)(&g_part[0][b * 2 + 1][k * DIM + d]) = z4;
    if (threadIdx.x == 0) {
        g_pcnt[0][b * 2 + 0][k] = 1;
        g_pcnt[0][b * 2 + 1][k] = 0;
    }
}

// FMA block: same-acc updates spaced 4 apart
#define FMABLOCK(C0, C1, C2, C3)                                              \
    _Pragma("unroll")                                                         \
    for (int k = 0; k < KCL; k++) {                                           \
        ulonglong2 cc = *(const ulonglong2*)(scd + (size_t)k * DIM);          \
        acc[k][0] = fma2((C0).x, cc.x, acc[k][0]);                            \
        acc[k][1] = fma2((C1).x, cc.x, acc[k][1]);                            \
        acc[k][2] = fma2((C2).x, cc.x, acc[k][2]);                            \
        acc[k][3] = fma2((C3).x, cc.x, acc[k][3]);                            \
        acc[k][0] = fma2((C0).y, cc.y, acc[k][0]);                            \
        acc[k][1] = fma2((C1).y, cc.y, acc[k][1]);                            \
        acc[k][2] = fma2((C2).y, cc.y, acc[k][2]);                            \
        acc[k][3] = fma2((C3).y, cc.y, acc[k][3]);                            \
    }

// ---------------- fused iteration: per-warp cp.async pipelines -------------
// grid = 128 (b, sp), block = 512, ~209KB smem, 1 CTA/SM.
// Phase A has NO CTA barriers: each warp streams its own 4 rows through a
// private 4-deep smem ring with per-thread cp.async waits.
__global__ __launch_bounds__(512, 1) void iter_kernel(const float* __restrict__ feats,
                                                      int rd) {
    extern __shared__ float smem[];
    float* sc     = smem;                              // [KCL][DIM] 80KB
    float* fbuf   = smem + KCL * DIM;                  // [16][NBUF][4][CHUNKF] 128KB
    float* schalf = fbuf + 16 * NBUF * 4 * CHUNKF;     // [16]
    float* sinv   = schalf + 16;                       // [16]
    int*   sa      = (int*)(sinv + 16);                // [TILE]
    int*   ssorted = sa + TILE;                        // [TILE]
    int*   soff    = ssorted + TILE;                   // [12]
    int*   srun    = soff + 12;                        // [10]
    int*   scnt    = srun + 10;                        // [16]

    int bid = blockIdx.x;
    int b = bid >> 1, sp = bid & 1;
    int wr = rd ^ 1;
    int tid = threadIdx.x, warp = tid >> 5, lane = tid & 31;
    float4 z4 = make_float4(0.f, 0.f, 0.f, 0.f);

    // per-warp ring base (bytes): warp * NBUF * 2KB
    unsigned int fba = (unsigned int)__cvta_generic_to_shared(fbuf)
                     + (unsigned int)(warp * NBUF * 4 * CHUNKF * 4);
    const float* frw = fbuf + (size_t)warp * NBUF * 4 * CHUNKF;   // float view

    // ---- fused reduce: centroids = (part0 + part1) * inv; zero wr slot -----
    if (tid < KCL) {
        int c = g_pcnt[rd][b * 2 + 0][tid] + g_pcnt[rd][b * 2 + 1][tid];
        sinv[tid] = 1.0f / (float)(c > 1 ? c : 1);
        scnt[tid] = 0;
    }
    __syncthreads();
    {
        const float4* q0 = (const float4*)g_part[rd][b * 2 + 0];
        const float4* q1 = (const float4*)g_part[rd][b * 2 + 1];
        float4* zw = (float4*)g_part[wr][bid];
        for (int i = tid; i < KCL * DIM / 4; i += 512) {
            float4 a = q0[i], c = q1[i];
            float inv = sinv[i >> 9];
            ((float4*)sc)[i] = make_float4((a.x + c.x) * inv, (a.y + c.y) * inv,
                                           (a.z + c.z) * inv, (a.w + c.w) * inv);
            zw[i] = z4;
        }
    }
    __syncthreads();

    if (warp < KCL) {
        float s = 0.f;
        for (int d = lane; d < DIM; d += 32) {
            float c = sc[warp * DIM + d];
            s = fmaf(c, c, s);
        }
        #pragma unroll
        for (int o = 16; o; o >>= 1) s += __shfl_xor_sync(0xffffffffu, s, o);
        if (lane == 0) schalf[warp] = 0.5f * s;
    }
    __syncthreads();

    const float* fb = feats + ((size_t)b * NPTS + (size_t)sp * NROWC) * DIM;
    int gabase = b * NPTS + sp * NROWC;
    int mywd = warp * 128 + lane * 4;                  // phase-B slice

    for (int tile = 0; tile < NTILES; tile++) {
        int tbase = tile * TILE;
        int nrows = NROWC - tbase; if (nrows > TILE) nrows = TILE;

        // warp's 4 rows (clamped)
        int r0i = tbase + warp * 4;
        const char* rp[4];
        #pragma unroll
        for (int r = 0; r < 4; r++) {
            int g = min(r0i + r, NROWC - 1);
            rp[r] = (const char*)(fb + (size_t)g * DIM) + lane * 16;
        }

        // ---------- prologue: issue chunks 0..2 into ring bufs 0..2 --------
        #pragma unroll
        for (int c = 0; c < 3; c++) {
            unsigned int dbase = fba + (unsigned int)(c * 4 * CHUNKF * 4);
            #pragma unroll
            for (int r = 0; r < 4; r++)
                cp16(dbase + (unsigned int)(r * CHUNKF * 4) + lane * 16,
                     rp[r] + c * (CHUNKF * 4));
            CP_COMMIT();
        }

        // ---------- phase A: per-warp pipelined FMA (no CTA barriers) -------
        unsigned long long acc[KCL][4];
        #pragma unroll
        for (int k = 0; k < KCL; k++)
            #pragma unroll
            for (int r = 0; r < 4; r++) acc[k][r] = 0ull;

        #pragma unroll 1
        for (int ch = 0; ch < NCHUNK; ch++) {
            CP_WAIT2();          // own group for chunk ch complete
            __syncwarp();

            const float* fr = frw + (size_t)(ch & 3) * (4 * CHUNKF) + lane * 4;
            ulonglong2 c0 = *(const ulonglong2*)(fr);
            ulonglong2 c1 = *(const ulonglong2*)(fr + CHUNKF);
            ulonglong2 c2 = *(const ulonglong2*)(fr + 2 * CHUNKF);
            ulonglong2 c3 = *(const ulonglong2*)(fr + 3 * CHUNKF);
            const float* scd = sc + ch * CHUNKF + lane * 4;
            FMABLOCK(c0, c1, c2, c3);

            if (ch < NCHUNK - 3) {
                int nc = ch + 3;
                unsigned int dbase = fba + (unsigned int)((nc & 3) * 4 * CHUNKF * 4);
                #pragma unroll
                for (int r = 0; r < 4; r++)
                    cp16(dbase + (unsigned int)(r * CHUNKF * 4) + lane * 16,
                         rp[r] + nc * (CHUNKF * 4));
            }
            CP_COMMIT();
        }

        // reduce + argmin
        float dot[KCL][4];
        #pragma unroll
        for (int k = 0; k < KCL; k++) {
            #pragma unroll
            for (int r = 0; r < 4; r++) {
                float2 v = unpack2(acc[k][r]);
                float s = v.x + v.y;
                #pragma unroll
                for (int o = 16; o; o >>= 1)
                    s += __shfl_xor_sync(0xffffffffu, s, o);
                dot[k][r] = s;
            }
        }
        #pragma unroll
        for (int r = 0; r < 4; r++) {
            if (lane == r) {
                float best = schalf[0] - dot[0][r];
                int bi = 0;
                #pragma unroll
                for (int k = 1; k < KCL; k++) {
                    float s = schalf[k] - dot[k][r];
                    if (s < best) { best = s; bi = k; }
                }
                bool valid = (r0i + r) < NROWC;
                sa[warp * 4 + r] = valid ? bi : -1;
                if (valid) g_assign[gabase + r0i + r] = bi;
            }
        }
        __syncthreads();   // sa complete (also protects soff/ssorted reuse)

        // ---------- counting sort (warp 0, two 32-wide passes) ----------
        if (warp == 0) {
            int mycnt = 0;
            #pragma unroll
            for (int q = 0; q < 2; q++) {
                int n = q * 32 + lane;
                int a = (n < nrows) ? sa[n] : -1;
                #pragma unroll
                for (int k = 0; k < KCL; k++) {
                    unsigned m = __ballot_sync(0xffffffffu, a == k);
                    if (lane == k) mycnt += __popc(m);
                }
            }
            int v = (lane < KCL) ? mycnt : 0;
            #pragma unroll
            for (int o = 1; o < 16; o <<= 1) {
                int t = __shfl_up_sync(0xffffffffu, v, o);
                if (lane >= o) v += t;
            }
            int excl = v - ((lane < KCL) ? mycnt : 0);
            if (lane < KCL) { soff[lane] = excl; srun[lane] = excl; scnt[lane] += mycnt; }
            if (lane == KCL - 1) soff[KCL] = v;
            __syncwarp();
            #pragma unroll
            for (int q = 0; q < 2; q++) {
                int n = q * 32 + lane;
                int a = (n < nrows) ? sa[n] : -1;
                unsigned mybal = 0;
                #pragma unroll
                for (int k = 0; k < KCL; k++) {
                    unsigned m = __ballot_sync(0xffffffffu, a == k);
                    if (a == k) mybal = m;
                }
                if (a >= 0) {
                    int rank = __popc(mybal & ((1u << lane) - 1u));
                    ssorted[srun[a] + rank] = n;
                    if (rank == __popc(mybal) - 1) srun[a] += rank + 1;
                }
                __syncwarp();
            }
        }
        __syncthreads();

        // ---------- phase B: sorted lists -> register sums -> g_part RMW ----
        {
            const float* fsl = fb + (size_t)tbase * DIM + mywd;
            float* gslice = &g_part[wr][bid][mywd];
            #pragma unroll
            for (int k = 0; k < KCL; k++) {
                int s0 = soff[k], s1 = soff[k + 1];
                if (s0 == s1) continue;
                float* gp = gslice + (size_t)k * DIM;
                float4 o0 = *(const float4*)gp;
                float4 a4 = z4, b4 = z4;
                int idx = s0;
                for (; idx + 2 <= s1; idx += 2) {
                    int na = ssorted[idx], nb = ssorted[idx + 1];
                    float4 fa = *(const float4*)(fsl + (size_t)na * DIM);
                    float4 fc = *(const float4*)(fsl + (size_t)nb * DIM);
                    a4.x += fa.x; a4.y += fa.y; a4.z += fa.z; a4.w += fa.w;
                    b4.x += fc.x; b4.y += fc.y; b4.z += fc.z; b4.w += fc.w;
                }
                if (idx < s1) {
                    int na = ssorted[idx];
                    float4 fa = *(const float4*)(fsl + (size_t)na * DIM);
                    a4.x += fa.x; a4.y += fa.y; a4.z += fa.z; a4.w += fa.w;
                }
                o0.x += a4.x + b4.x; o0.y += a4.y + b4.y;
                o0.z += a4.z + b4.z; o0.w += a4.w + b4.w;
                *(float4*)gp = o0;
            }
        }
        // no trailing barrier: next tile's sa-barrier provides ordering
    }

    __syncthreads();
    if (tid < KCL) g_pcnt[wr][bid][tid] = scnt[tid];
}

// ---------------- final GeM pooling (empty cluster -> 0) ----------------
__global__ __launch_bounds__(512) void final_kernel(const float* __restrict__ feats,
                                                    const float* __restrict__ pp,
                                                    float* __restrict__ out) {
    __shared__ int sa[NPTS];
    int b = blockIdx.x / KCL, k = blockIdx.x % KCL;
    int tid = threadIdx.x;
    for (int i = tid; i < NPTS; i += 512) sa[i] = g_assign[b * NPTS + i];
    __syncthreads();

    float pv = pp[0];
    bool p3 = (pv == 3.0f);
    const float* fb = feats + (size_t)b * NPTS * DIM + tid * 4;

    float ax = 0.f, ay = 0.f, az = 0.f, aw = 0.f;
    int cnt = 0;
    if (p3) {
        #pragma unroll 2
        for (int n = 0; n < NPTS; n++) {
            if (sa[n] == k) {
                cnt++;
                float4 f = *(const float4*)(fb + (size_t)n * DIM);
                float x = fmaxf(f.x, EPSV), y = fmaxf(f.y, EPSV);
                float z = fmaxf(f.z, EPSV), w = fmaxf(f.w, EPSV);
                ax += x * x * x; ay += y * y * y; az += z * z * z; aw += w * w * w;
            }
        }
    } else {
        for (int n = 0; n < NPTS; n++) {
            if (sa[n] == k) {
                cnt++;
                float4 f = *(const float4*)(fb + (size_t)n * DIM);
                ax += powf(fmaxf(f.x, EPSV), pv);
                ay += powf(fmaxf(f.y, EPSV), pv);
                az += powf(fmaxf(f.z, EPSV), pv);
                aw += powf(fmaxf(f.w, EPSV), pv);
            }
        }
    }

    float inv = 1.0f / (float)(cnt > 1 ? cnt : 1);
    size_t oi = (size_t)(b * KCL + k) * DIM + tid * 4;
    float4 o;
    if (cnt > 0) {
        if (p3) {
            o = make_float4(cbrtf(ax * inv), cbrtf(ay * inv),
                            cbrtf(az * inv), cbrtf(aw * inv));
        } else {
            float ip = 1.0f / pv;
            o = make_float4(powf(ax * inv, ip), powf(ay * inv, ip),
                            powf(az * inv, ip), powf(aw * inv, ip));
        }
    } else {
        o = make_float4(0.f, 0.f, 0.f, 0.f);
    }
    *(float4*)(out + oi) = o;
}

// ---------------- launch ----------------
extern "C" void kernel_launch(void* const* d_in, const int* in_sizes, int n_in,
                              void* d_out, int out_size) {
    const float* feats = (const float*)d_in[0];
    const float* p     = (const float*)d_in[1];
    float* out         = (float*)d_out;

    const int smem_iter = (KCL * DIM + 16 * NBUF * 4 * CHUNKF + 32) * sizeof(float)
                        + (TILE + TILE + 12 + 10 + 16) * sizeof(int);
    cudaFuncSetAttribute(iter_kernel,
                         cudaFuncAttributeMaxDynamicSharedMemorySize, smem_iter);

    init_kernel<<<NBATCH * KCL, 512>>>(feats);
    for (int it = 0; it < NITER; it++)
        iter_kernel<<<NBATCH * NSPLIT, 512, smem_iter>>>(feats, it & 1);
    final_kernel<<<NBATCH * KCL, 512>>>(feats, p, out);
}